// round 13
// baseline (speedup 1.0000x reference)
#include <cuda_runtime.h>
#include <cstdint>

// GaussianKDE via legacy mma.sync tf32 + WARP-SPECIALIZED exp epilogue.
// 4 producer warps (MMA only) + 4 consumer warps (exp epilogue only); one of
// each per SMSP so the HW scheduler overlaps tensor and MUFU pipes.
// Handshake: named barriers (full/empty per S buffer), S double-buffered.
// out[q] = (norm/N) * a[q] * sum_n b[n] * exp2((log2e*f_q) . x_n)

#define DCONST 64
#define QCAP   4096
#define NCAP   50048        // 782 * 64
#define QTILE  128
#define NTILE  64
#define NCHUNK 9            // 32 q-tiles * 9 = 288 blocks ~= 2 waves * 148 SMs
#define XS     68
#define LOG2E  1.44269504088896340736f
#define MAXT   88           // max 64-col tiles per block chunk (782/9 -> 87)

#define F_B  (128 * XS * 4)             // 34816
#define X_B  (64 * XS * 4)              // 17408
#define S_B  (128 * XS * 4)             // 34816
#define OFF_F  0
#define OFF_X  (OFF_F + F_B)            // 2 buffers
#define OFF_S  (OFF_X + 2 * X_B)        // 2 buffers
#define OFF_BS (OFF_S + 2 * S_B)        // whole-chunk b[] slice
#define SMEM_TOTAL (OFF_BS + MAXT * 64 * 4)   // 161792 B

__device__ float g_fhi[QCAP * DCONST];   // tf32(log2e * f)
__device__ float g_a[QCAP];
__device__ float g_xhi[NCAP * DCONST];   // tf32(x)
__device__ float g_b[NCAP];

// ---------------------------------------------------------------------------
__device__ __forceinline__ uint32_t smem_u32(const void* p) {
    uint32_t a;
    asm("{ .reg .u64 t; cvta.to.shared.u64 t, %1; cvt.u32.u64 %0, t; }"
        : "=r"(a) : "l"(p));
    return a;
}
__device__ __forceinline__ void cp16(uint32_t dst, const void* src) {
    asm volatile("cp.async.cg.shared.global [%0], [%1], 16;"
                 :: "r"(dst), "l"(src) : "memory");
}
__device__ __forceinline__ void mma8(float* d, const uint32_t* a,
                                     uint32_t b0, uint32_t b1) {
    asm volatile("mma.sync.aligned.m16n8k8.row.col.f32.tf32.tf32.f32 "
                 "{%0,%1,%2,%3}, {%4,%5,%6,%7}, {%8,%9}, {%0,%1,%2,%3};"
                 : "+f"(d[0]), "+f"(d[1]), "+f"(d[2]), "+f"(d[3])
                 : "r"(a[0]), "r"(a[1]), "r"(a[2]), "r"(a[3]),
                   "r"(b0), "r"(b1));
}
__device__ __forceinline__ uint32_t to_tf32_bits(float x) {
    uint32_t r;
    asm("cvt.rna.tf32.f32 %0, %1;" : "=r"(r) : "f"(x));
    return r;
}
__device__ __forceinline__ float ex2(float x) {
    float r;
    asm("ex2.approx.f32 %0, %1;" : "=f"(r) : "f"(x));
    return r;
}
#define BAR_SYNC(id, n)   asm volatile("bar.sync %0, %1;"   :: "r"(id), "r"(n) : "memory")
#define BAR_ARRIVE(id, n) asm volatile("bar.arrive %0, %1;" :: "r"(id), "r"(n) : "memory")

// ---------------------------------------------------------------------------
// Fused prep: blocks [0, FB) do the F side, blocks [FB, ...) the X side.
__global__ void prep_kernel(const float* __restrict__ feat,
                            const float* __restrict__ bw,
                            const float* __restrict__ ds,
                            float* __restrict__ out, int Q, int N, int FB) {
    int tid = threadIdx.x;
    if ((int)blockIdx.x < FB) {
        __shared__ float bws[DCONST][DCONST];
        for (int i = tid; i < DCONST * DCONST; i += 256)
            bws[i / DCONST][i % DCONST] = bw[i];
        __syncthreads();
        int q = blockIdx.x * 256 + tid;
        if (q >= Q) return;

        float r[DCONST];
        const float4* fr = (const float4*)(feat + (size_t)q * DCONST);
#pragma unroll
        for (int v = 0; v < DCONST / 4; v++) {
            float4 t = fr[v];
            r[4 * v + 0] = t.x; r[4 * v + 1] = t.y;
            r[4 * v + 2] = t.z; r[4 * v + 3] = t.w;
        }
        float f2 = 0.0f;
#pragma unroll 4
        for (int d = 0; d < DCONST; d++) {
            float acc = 0.0f;
#pragma unroll
            for (int k = 0; k < DCONST; k++) acc = fmaf(r[k], bws[k][d], acc);
            g_fhi[(size_t)q * DCONST + d] =
                __uint_as_float(to_tf32_bits(acc * LOG2E));
            f2 = fmaf(acc, acc, f2);
        }
        g_a[q] = expf(-0.5f * f2);
        out[q] = 0.0f;
    } else {
        int n = (blockIdx.x - FB) * 256 + tid;
        if (n >= NCAP) return;
        if (n < N) {
            float x2 = 0.0f;
            const float4* r4 = (const float4*)(ds + (size_t)n * DCONST);
#pragma unroll
            for (int v = 0; v < DCONST / 4; v++) {
                float4 t = r4[v];
                float e[4] = {t.x, t.y, t.z, t.w};
#pragma unroll
                for (int j = 0; j < 4; j++) {
                    g_xhi[(size_t)n * DCONST + 4 * v + j] =
                        __uint_as_float(to_tf32_bits(e[j]));
                    x2 = fmaf(e[j], e[j], x2);
                }
            }
            g_b[n] = expf(-0.5f * x2);
        } else {
#pragma unroll
            for (int v = 0; v < DCONST / 4; v++)
                *(float4*)(g_xhi + (size_t)n * DCONST + 4 * v) =
                    make_float4(0, 0, 0, 0);
            g_b[n] = 0.0f;
        }
    }
}

// ---------------------------------------------------------------------------
// Main kernel: 128(Q) x 64(N) tile per step, 256 threads.
// Warps 0-3: producers (MMA -> S smem). Warps 4-7: consumers (ex2 epilogue).
// Named barriers: full[p]=4+p, empty[p]=2+p (count 256); producer X sync: 6
// (count 128); consumer bs sync: 7 (count 128).
__global__ __launch_bounds__(256, 1) void kde_mma_kernel(
    const float* __restrict__ norm, float* __restrict__ out,
    int Q, int N, int NT) {
    extern __shared__ char smem[];
    const uint32_t sb = smem_u32(smem);
    const int tid = threadIdx.x, lane = tid & 31, wid = tid >> 5;
    const int q0 = blockIdx.x * QTILE;
    const int t0 = (blockIdx.y * NT) / NCHUNK;
    const int t1 = ((blockIdx.y + 1) * NT) / NCHUNK;
    const int cnt = t1 - t0;

    if (wid < 4) {
        // ================= PRODUCER =================
        const int ptid = tid;             // 0..127
        // Stage F tile + first X tile (one cp.async group).
#pragma unroll
        for (int i = 0; i < 16; i++) {
            int e = ptid + (i << 7);
            int row = e >> 4, c = e & 15;
            cp16(sb + OFF_F + row * (XS * 4) + c * 16,
                 g_fhi + (size_t)(q0 + row) * DCONST + c * 4);
        }
        {
            int n0 = t0 * NTILE;
#pragma unroll
            for (int i = 0; i < 8; i++) {
                int e = ptid + (i << 7);
                int row = e >> 4, c = e & 15;
                cp16(sb + OFF_X + row * (XS * 4) + c * 16,
                     g_xhi + (size_t)(n0 + row) * DCONST + c * 4);
            }
        }
        asm volatile("cp.async.commit_group;");

        const float* fh = (const float*)(smem + OFF_F);
        const int rA = wid * 32 + (lane >> 2);
        const int cA = lane & 3;
        const int colB = lane >> 2;

        uint32_t ah[2][8][4];
        bool a_loaded = false;

        for (int j = 0; j < cnt; j++) {
            const int p = j & 1;
            if (j + 1 < cnt) {
                int n0 = (t0 + j + 1) * NTILE;
                int bb = (j + 1) & 1;
#pragma unroll
                for (int i = 0; i < 8; i++) {
                    int e = ptid + (i << 7);
                    int row = e >> 4, c = e & 15;
                    cp16(sb + OFF_X + bb * X_B + row * (XS * 4) + c * 16,
                         g_xhi + (size_t)(n0 + row) * DCONST + c * 4);
                }
                asm volatile("cp.async.commit_group;");
                asm volatile("cp.async.wait_group 1;");
            } else {
                asm volatile("cp.async.wait_group 0;");
            }
            BAR_SYNC(6, 128);            // X[j&1] visible to all producers

            if (!a_loaded) {
                a_loaded = true;
#pragma unroll
                for (int qs = 0; qs < 2; qs++)
#pragma unroll
                    for (int kk = 0; kk < 8; kk++) {
                        const float* pp = fh + (rA + qs * 16) * XS + kk * 8 + cA;
                        ah[qs][kk][0] = __float_as_uint(pp[0]);
                        ah[qs][kk][1] = __float_as_uint(pp[8 * XS]);
                        ah[qs][kk][2] = __float_as_uint(pp[4]);
                        ah[qs][kk][3] = __float_as_uint(pp[8 * XS + 4]);
                    }
            }

            if (j >= 2) BAR_SYNC(2 + p, 256);   // wait S[p] consumed

            const float* xp = (const float*)(smem + OFF_X + p * X_B);
            float acc[2][8][4];
#pragma unroll
            for (int qs = 0; qs < 2; qs++)
#pragma unroll
                for (int ns = 0; ns < 8; ns++)
#pragma unroll
                    for (int i = 0; i < 4; i++) acc[qs][ns][i] = 0.f;

#pragma unroll
            for (int kk = 0; kk < 8; kk++) {
#pragma unroll
                for (int ns = 0; ns < 8; ns++) {
                    const float* pb = xp + (ns * 8 + colB) * XS + kk * 8 + cA;
                    uint32_t b0 = __float_as_uint(pb[0]);
                    uint32_t b1 = __float_as_uint(pb[4]);
                    mma8(acc[0][ns], ah[0][kk], b0, b1);
                    mma8(acc[1][ns], ah[1][kk], b0, b1);
                }
            }

            // Store S tile (mma fragment layout -> [row][col], stride XS)
            float* Sp = (float*)(smem + OFF_S + p * S_B);
#pragma unroll
            for (int qs = 0; qs < 2; qs++)
#pragma unroll
                for (int ns = 0; ns < 8; ns++) {
                    int row0 = rA + qs * 16;
                    int col = ns * 8 + 2 * cA;
                    *(float2*)(Sp + row0 * XS + col) =
                        make_float2(acc[qs][ns][0], acc[qs][ns][1]);
                    *(float2*)(Sp + (row0 + 8) * XS + col) =
                        make_float2(acc[qs][ns][2], acc[qs][ns][3]);
                }
            BAR_ARRIVE(4 + p, 256);      // S[p] full
        }
    } else {
        // ================= CONSUMER =================
        const int ctid = tid - 128;       // 0..127
        const int row = (wid - 4) * 32 + lane;   // this thread's q row

        // Preload the whole chunk's b[] slice.
        {
            int nf4 = cnt * 16;           // float4 count
            for (int i = ctid; i < nf4; i += 128)
                cp16(sb + OFF_BS + i * 16, g_b + (size_t)t0 * NTILE + i * 4);
            asm volatile("cp.async.commit_group;");
            asm volatile("cp.async.wait_group 0;");
            BAR_SYNC(7, 128);
        }
        const float* bsb = (const float*)(smem + OFF_BS);
        float racc = 0.0f;

        for (int j = 0; j < cnt; j++) {
            const int p = j & 1;
            BAR_SYNC(4 + p, 256);        // wait S[p] full
            const float* sp = (const float*)(smem + OFF_S + p * S_B) + row * XS;
            const float* bp = bsb + j * 64;
#pragma unroll
            for (int c = 0; c < 16; c++) {
                float4 s = *(const float4*)(sp + c * 4);
                float4 b = *(const float4*)(bp + c * 4);
                racc += b.x * ex2(s.x) + b.y * ex2(s.y) +
                        b.z * ex2(s.z) + b.w * ex2(s.w);
            }
            BAR_ARRIVE(2 + p, 256);      // S[p] empty
        }

        int q = q0 + row;
        if (q < Q)
            atomicAdd(&out[q], racc * g_a[q] * (__ldg(norm) / (float)N));
    }
}

// ---------------------------------------------------------------------------
extern "C" void kernel_launch(void* const* d_in, const int* in_sizes, int n_in,
                              void* d_out, int out_size) {
    const float* features = (const float*)d_in[0];
    const float* bw       = (const float*)d_in[1];
    const float* dataset  = (const float*)d_in[2];
    const float* norm     = (const float*)d_in[3];

    int Q = in_sizes[0] / DCONST;
    int N = in_sizes[2] / DCONST;
    int NT = (N + NTILE - 1) / NTILE;     // 64-col tiles
    float* out = (float*)d_out;

    cudaFuncSetAttribute(kde_mma_kernel,
                         cudaFuncAttributeMaxDynamicSharedMemorySize, SMEM_TOTAL);

    int FB = (Q + 255) / 256;
    int XB = (NCAP + 255) / 256;
    prep_kernel<<<FB + XB, 256>>>(features, bw, dataset, out, Q, N, FB);

    dim3 grid((Q + QTILE - 1) / QTILE, NCHUNK);
    kde_mma_kernel<<<grid, 256, SMEM_TOTAL>>>(norm, out, Q, N, NT);
}

// round 14
// speedup vs baseline: 1.8575x; 1.8575x over previous
#include <cuda_runtime.h>
#include <cuda_fp16.h>
#include <cstdint>

// GaussianKDE via legacy mma.sync fp16 m16n8k16 (fp32 accum) + fused exp epilogue.
// R11 structure (best known), dtype swapped tf32->fp16: same 10-bit mantissa,
// half the MMA instructions (K=16 per mma), half the LDS and smem.
// out[q] = (norm/N) * a[q] * sum_n b[n] * exp2((log2e*f_q) . x_n)

#define DCONST 64
#define QCAP   4096
#define NCAP   50048        // 391 * 128
#define QTILE  128
#define NTILE  128
#define NCHUNK 9            // 32 q-tiles * 9 = 288 blocks ~= 2 waves * 148 SMs
#define XS2    36           // uint32 (fp16x2) row stride: 32 pairs + 4 pad
#define LOG2E  1.44269504088896340736f

#define OFF_F  0
#define TILE_B (128 * XS2 * 4)          // 18432 bytes per 128-row fp16 tile
#define OFF_X  (OFF_F + TILE_B)         // 2 buffers
#define OFF_BS (OFF_X + 2 * TILE_B)     // bs[2][128] floats
#define OFF_RED (OFF_BS + 1024)         // red[256] floats
#define SMEM_TOTAL (OFF_RED + 1024)     // ~57 KB

__device__ uint32_t g_fh[QCAP * 32];    // fp16x2(log2e * f), pairs (2p, 2p+1)
__device__ float    g_a[QCAP];
__device__ uint32_t g_xh[NCAP * 32];    // fp16x2(x)
__device__ float    g_b[NCAP];

// ---------------------------------------------------------------------------
__device__ __forceinline__ uint32_t smem_u32(const void* p) {
    uint32_t a;
    asm("{ .reg .u64 t; cvta.to.shared.u64 t, %1; cvt.u32.u64 %0, t; }"
        : "=r"(a) : "l"(p));
    return a;
}
__device__ __forceinline__ void cp16(uint32_t dst, const void* src) {
    asm volatile("cp.async.cg.shared.global [%0], [%1], 16;"
                 :: "r"(dst), "l"(src) : "memory");
}
__device__ __forceinline__ void mma16(float* d, const uint32_t* a,
                                      uint32_t b0, uint32_t b1) {
    asm volatile("mma.sync.aligned.m16n8k16.row.col.f32.f16.f16.f32 "
                 "{%0,%1,%2,%3}, {%4,%5,%6,%7}, {%8,%9}, {%0,%1,%2,%3};"
                 : "+f"(d[0]), "+f"(d[1]), "+f"(d[2]), "+f"(d[3])
                 : "r"(a[0]), "r"(a[1]), "r"(a[2]), "r"(a[3]),
                   "r"(b0), "r"(b1));
}
__device__ __forceinline__ uint32_t pack_h2(float lo, float hi) {
    __half2 h = __floats2half2_rn(lo, hi);   // x = lo (low 16 bits)
    return *(uint32_t*)&h;
}
__device__ __forceinline__ float ex2(float x) {
    float r;
    asm("ex2.approx.f32 %0, %1;" : "=f"(r) : "f"(x));
    return r;
}

// ---------------------------------------------------------------------------
// Fused prep: blocks [0, FB) do the F side, blocks [FB, ...) the X side.
__global__ void prep_kernel(const float* __restrict__ feat,
                            const float* __restrict__ bw,
                            const float* __restrict__ ds,
                            float* __restrict__ out, int Q, int N, int FB) {
    int tid = threadIdx.x;
    if ((int)blockIdx.x < FB) {
        // F side: f = feat @ bw; store fp16x2(log2e*f); a[q]; zero out[q].
        __shared__ float bws[DCONST][DCONST];
        for (int i = tid; i < DCONST * DCONST; i += 256)
            bws[i / DCONST][i % DCONST] = bw[i];
        __syncthreads();
        int q = blockIdx.x * 256 + tid;
        if (q >= Q) return;

        float r[DCONST];
        const float4* fr = (const float4*)(feat + (size_t)q * DCONST);
#pragma unroll
        for (int v = 0; v < DCONST / 4; v++) {
            float4 t = fr[v];
            r[4 * v + 0] = t.x; r[4 * v + 1] = t.y;
            r[4 * v + 2] = t.z; r[4 * v + 3] = t.w;
        }
        float fv[DCONST];
        float f2 = 0.0f;
#pragma unroll 4
        for (int d = 0; d < DCONST; d++) {
            float acc = 0.0f;
#pragma unroll
            for (int k = 0; k < DCONST; k++) acc = fmaf(r[k], bws[k][d], acc);
            fv[d] = acc * LOG2E;
            f2 = fmaf(acc, acc, f2);
        }
#pragma unroll
        for (int p = 0; p < 32; p++)
            g_fh[(size_t)q * 32 + p] = pack_h2(fv[2 * p], fv[2 * p + 1]);
        g_a[q] = expf(-0.5f * f2);
        out[q] = 0.0f;
    } else {
        // X side: fp16x2(x); b[n]; zero-pad rows [N, NCAP).
        int n = (blockIdx.x - FB) * 256 + tid;
        if (n >= NCAP) return;
        if (n < N) {
            float x2 = 0.0f;
            const float4* r4 = (const float4*)(ds + (size_t)n * DCONST);
#pragma unroll
            for (int v = 0; v < DCONST / 4; v++) {
                float4 t = r4[v];
                g_xh[(size_t)n * 32 + 2 * v + 0] = pack_h2(t.x, t.y);
                g_xh[(size_t)n * 32 + 2 * v + 1] = pack_h2(t.z, t.w);
                x2 = fmaf(t.x, t.x, x2); x2 = fmaf(t.y, t.y, x2);
                x2 = fmaf(t.z, t.z, x2); x2 = fmaf(t.w, t.w, x2);
            }
            g_b[n] = expf(-0.5f * x2);
        } else {
            uint4 z = make_uint4(0, 0, 0, 0);
#pragma unroll
            for (int i = 0; i < 8; i++)
                *(uint4*)(g_xh + (size_t)n * 32 + 4 * i) = z;
            g_b[n] = 0.0f;
        }
    }
}

// ---------------------------------------------------------------------------
// Main kernel: 128(Q) x 128(N) tile per block, 256 threads (8 warps).
// Warp = 32(Q) x 64(N): wq = wid>>1, wn = wid&1. K=64 as 4 m16n8k16 steps.
// A fragments (32 regs) preloaded once per block.
__global__ __launch_bounds__(256, 1) void kde_mma_kernel(
    const float* __restrict__ norm, float* __restrict__ out,
    int Q, int N, int NT) {
    extern __shared__ char smem[];
    const uint32_t sb = smem_u32(smem);
    const uint32_t* fhu = (const uint32_t*)(smem + OFF_F);
    const int tid = threadIdx.x, lane = tid & 31, wid = tid >> 5;
    const int wq = wid >> 1, wn = wid & 1;
    const int q0 = blockIdx.x * QTILE;
    const int t0 = (blockIdx.y * NT) / NCHUNK;
    const int t1 = ((blockIdx.y + 1) * NT) / NCHUNK;
    const int cnt = t1 - t0;

    // Stage F tile and first X tile via cp.async. Rows: 128B data, 144B stride.
#pragma unroll
    for (int i = 0; i < 4; i++) {
        int e = tid + (i << 8);
        int row = e >> 3, c = e & 7;
        cp16(sb + OFF_F + row * (XS2 * 4) + c * 16,
             g_fh + (size_t)(q0 + row) * 32 + c * 4);
    }
    {
        int n0 = t0 * NTILE;
#pragma unroll
        for (int i = 0; i < 4; i++) {
            int e = tid + (i << 8);
            int row = e >> 3, c = e & 7;
            cp16(sb + OFF_X + row * (XS2 * 4) + c * 16,
                 g_xh + (size_t)(n0 + row) * 32 + c * 4);
        }
        if (tid < 32) cp16(sb + OFF_BS + tid * 16, g_b + n0 + tid * 4);
    }
    asm volatile("cp.async.commit_group;");

    const int rA = wq * 32 + (lane >> 2);
    const int cA = lane & 3;
    const int colB = lane >> 2;

    uint32_t ah[2][4][4];     // A fragments, 4 k-steps, register-resident
    bool a_loaded = false;
    float racc[2][2] = {{0.f, 0.f}, {0.f, 0.f}};

    for (int j = 0; j < cnt; j++) {
        const int b = j & 1;
        if (j + 1 < cnt) {
            // Prefetch next X tile into the other buffer.
            int n0 = (t0 + j + 1) * NTILE;
            int bb = (j + 1) & 1;
#pragma unroll
            for (int i = 0; i < 4; i++) {
                int e = tid + (i << 8);
                int row = e >> 3, c = e & 7;
                cp16(sb + OFF_X + bb * TILE_B + row * (XS2 * 4) + c * 16,
                     g_xh + (size_t)(n0 + row) * 32 + c * 4);
            }
            if (tid < 32) cp16(sb + OFF_BS + bb * 512 + tid * 16, g_b + n0 + tid * 4);
            asm volatile("cp.async.commit_group;");
            asm volatile("cp.async.wait_group 1;");
        } else {
            asm volatile("cp.async.wait_group 0;");
        }
        __syncthreads();

        if (!a_loaded) {    // F tile resident after first wait
            a_loaded = true;
#pragma unroll
            for (int qs = 0; qs < 2; qs++)
#pragma unroll
                for (int kk = 0; kk < 4; kk++) {
                    const uint32_t* p = fhu + (rA + qs * 16) * XS2 + kk * 8 + cA;
                    ah[qs][kk][0] = p[0];
                    ah[qs][kk][1] = p[8 * XS2];
                    ah[qs][kk][2] = p[4];
                    ah[qs][kk][3] = p[8 * XS2 + 4];
                }
        }

        const uint32_t* xp = (const uint32_t*)(smem + OFF_X + b * TILE_B);
        float acc[2][8][4];
#pragma unroll
        for (int qs = 0; qs < 2; qs++)
#pragma unroll
            for (int ns = 0; ns < 8; ns++)
#pragma unroll
                for (int i = 0; i < 4; i++) acc[qs][ns][i] = 0.f;

#pragma unroll
        for (int kk = 0; kk < 4; kk++) {
#pragma unroll
            for (int ns = 0; ns < 8; ns++) {
                const uint32_t* pb = xp + (wn * 64 + ns * 8 + colB) * XS2 + kk * 8;
                uint32_t b0 = pb[cA];
                uint32_t b1 = pb[cA + 4];
                mma16(acc[0][ns], ah[0][kk], b0, b1);
                mma16(acc[1][ns], ah[1][kk], b0, b1);
            }
        }

        // Fused epilogue: racc += b[n] * exp2(s). Padded rows: s=0, b=0 -> no-op.
        const float* bsp = (const float*)(smem + OFF_BS + b * 512)
                           + wn * 64 + 2 * (lane & 3);
#pragma unroll
        for (int ns = 0; ns < 8; ns++) {
            float2 bv = *(const float2*)(bsp + ns * 8);
            racc[0][0] += bv.x * ex2(acc[0][ns][0]) + bv.y * ex2(acc[0][ns][1]);
            racc[0][1] += bv.x * ex2(acc[0][ns][2]) + bv.y * ex2(acc[0][ns][3]);
            racc[1][0] += bv.x * ex2(acc[1][ns][0]) + bv.y * ex2(acc[1][ns][1]);
            racc[1][1] += bv.x * ex2(acc[1][ns][2]) + bv.y * ex2(acc[1][ns][3]);
        }
        __syncthreads();   // compute done before buffer b is overwritten
    }

    // Reduce across the 4 lanes sharing each output row.
#pragma unroll
    for (int qs = 0; qs < 2; qs++)
#pragma unroll
        for (int h = 0; h < 2; h++) {
            float v = racc[qs][h];
            v += __shfl_xor_sync(0xffffffff, v, 1);
            v += __shfl_xor_sync(0xffffffff, v, 2);
            racc[qs][h] = v;
        }
    float* red = (float*)(smem + OFF_RED);
    if ((lane & 3) == 0) {
        int r = lane >> 2;
#pragma unroll
        for (int qs = 0; qs < 2; qs++)
#pragma unroll
            for (int h = 0; h < 2; h++)
                red[wn * 128 + wq * 32 + qs * 16 + h * 8 + r] = racc[qs][h];
    }
    __syncthreads();
    if (tid < 128) {
        int q = q0 + tid;
        if (q < Q) {
            float s = red[tid] + red[128 + tid];
            atomicAdd(&out[q], s * g_a[q] * (__ldg(norm) / (float)N));
        }
    }
}

// ---------------------------------------------------------------------------
extern "C" void kernel_launch(void* const* d_in, const int* in_sizes, int n_in,
                              void* d_out, int out_size) {
    const float* features = (const float*)d_in[0];
    const float* bw       = (const float*)d_in[1];
    const float* dataset  = (const float*)d_in[2];
    const float* norm     = (const float*)d_in[3];

    int Q = in_sizes[0] / DCONST;
    int N = in_sizes[2] / DCONST;
    int NT = (N + NTILE - 1) / NTILE;
    float* out = (float*)d_out;

    cudaFuncSetAttribute(kde_mma_kernel,
                         cudaFuncAttributeMaxDynamicSharedMemorySize, SMEM_TOTAL);

    int FB = (Q + 255) / 256;
    int XB = (NCAP + 255) / 256;
    prep_kernel<<<FB + XB, 256>>>(features, bw, dataset, out, Q, N, FB);

    dim3 grid((Q + QTILE - 1) / QTILE, NCHUNK);
    kde_mma_kernel<<<grid, 256, SMEM_TOTAL>>>(norm, out, Q, N, NT);
}